// round 2
// baseline (speedup 1.0000x reference)
#include <cuda_runtime.h>
#include <cuda_bf16.h>
#include <math_constants.h>

#define B_DIM 64
#define S_DIM 512
#define H_DIM 4096
#define WARPS_PER_BLOCK 8
#define THREADS (WARPS_PER_BLOCK * 32)
#define ROWS_PER_WARP 2
#define S_PER_BLOCK (WARPS_PER_BLOCK * ROWS_PER_WARP)   // 16
#define CHUNKS (S_DIM / S_PER_BLOCK)                     // 32 blocks per batch

// Scratch (no cudaMalloc allowed): energies [B, S] + per-batch completion counters
__device__ float        g_energies[B_DIM * S_DIM];
__device__ unsigned int g_counter[B_DIM];   // zero-initialized; reset by last block each run

__global__ __launch_bounds__(THREADS)
void fused_kernel(const float* __restrict__ questions,
                  const float* __restrict__ facts,
                  float* __restrict__ out) {
    __shared__ float4 sq[H_DIM / 4];          // 16 KB question row
    __shared__ float  red[WARPS_PER_BLOCK];
    __shared__ float  bcast;
    __shared__ int    is_last;

    const int b      = blockIdx.x / CHUNKS;
    const int schunk = blockIdx.x % CHUNKS;
    const int tid    = threadIdx.x;
    const int warp   = tid >> 5;
    const int lane   = tid & 31;

    // Stage this batch's question row into shared memory
    const float4* qv = reinterpret_cast<const float4*>(questions + (size_t)b * H_DIM);
    #pragma unroll
    for (int i = tid; i < H_DIM / 4; i += THREADS)
        sq[i] = qv[i];
    __syncthreads();

    // ---- energies: each warp computes ROWS_PER_WARP dot products over H=4096 ----
    #pragma unroll
    for (int t = 0; t < ROWS_PER_WARP; ++t) {
        const int s = schunk * S_PER_BLOCK + t * WARPS_PER_BLOCK + warp;
        const float4* fv = reinterpret_cast<const float4*>(
            facts + ((size_t)b * S_DIM + s) * H_DIM);

        float a0 = 0.f, a1 = 0.f, a2 = 0.f, a3 = 0.f;
        #pragma unroll
        for (int j = 0; j < (H_DIM / 4) / 32; j += 4) {
            float4 f0 = fv[(j + 0) * 32 + lane];
            float4 f1 = fv[(j + 1) * 32 + lane];
            float4 f2 = fv[(j + 2) * 32 + lane];
            float4 f3 = fv[(j + 3) * 32 + lane];
            float4 q0 = sq[(j + 0) * 32 + lane];
            float4 q1 = sq[(j + 1) * 32 + lane];
            float4 q2 = sq[(j + 2) * 32 + lane];
            float4 q3 = sq[(j + 3) * 32 + lane];
            a0 = fmaf(f0.x, q0.x, fmaf(f0.y, q0.y, fmaf(f0.z, q0.z, fmaf(f0.w, q0.w, a0))));
            a1 = fmaf(f1.x, q1.x, fmaf(f1.y, q1.y, fmaf(f1.z, q1.z, fmaf(f1.w, q1.w, a1))));
            a2 = fmaf(f2.x, q2.x, fmaf(f2.y, q2.y, fmaf(f2.z, q2.z, fmaf(f2.w, q2.w, a2))));
            a3 = fmaf(f3.x, q3.x, fmaf(f3.y, q3.y, fmaf(f3.z, q3.z, fmaf(f3.w, q3.w, a3))));
        }
        float acc = (a0 + a1) + (a2 + a3);
        #pragma unroll
        for (int off = 16; off > 0; off >>= 1)
            acc += __shfl_xor_sync(0xffffffffu, acc, off);
        if (lane == 0)
            g_energies[b * S_DIM + s] = acc;
    }

    // ---- publish: last block of this batch performs the softmax ----
    __syncthreads();                 // all warps' energy stores issued
    if (tid == 0) {
        __threadfence();             // make this block's energies visible device-wide
        unsigned prev = atomicAdd(&g_counter[b], 1u);
        is_last = (prev == CHUNKS - 1);
        if (is_last) {
            g_counter[b] = 0;        // reset for next graph replay (no contention now)
            __threadfence();         // acquire: order subsequent reads after the atomic
        }
    }
    __syncthreads();
    if (!is_last) return;

    // ---- softmax over the batch's 512 energies (256 threads, 2 elems each) ----
    float e0 = __ldcg(&g_energies[b * S_DIM + tid]);
    float e1 = __ldcg(&g_energies[b * S_DIM + tid + THREADS]);

    // max reduce
    float m = fmaxf(e0, e1);
    #pragma unroll
    for (int off = 16; off > 0; off >>= 1)
        m = fmaxf(m, __shfl_xor_sync(0xffffffffu, m, off));
    if (lane == 0) red[warp] = m;
    __syncthreads();
    if (tid < 32) {
        float v = (lane < WARPS_PER_BLOCK) ? red[lane] : -CUDART_INF_F;
        #pragma unroll
        for (int off = 16; off > 0; off >>= 1)
            v = fmaxf(v, __shfl_xor_sync(0xffffffffu, v, off));
        if (lane == 0) bcast = v;
    }
    __syncthreads();
    const float row_max = bcast;

    // exp + sum reduce
    float x0 = __expf(e0 - row_max);
    float x1 = __expf(e1 - row_max);
    float ssum = x0 + x1;
    #pragma unroll
    for (int off = 16; off > 0; off >>= 1)
        ssum += __shfl_xor_sync(0xffffffffu, ssum, off);
    __syncthreads();
    if (lane == 0) red[warp] = ssum;
    __syncthreads();
    if (tid < 32) {
        float v = (lane < WARPS_PER_BLOCK) ? red[lane] : 0.f;
        #pragma unroll
        for (int off = 16; off > 0; off >>= 1)
            v += __shfl_xor_sync(0xffffffffu, v, off);
        if (lane == 0) bcast = v;
    }
    __syncthreads();
    const float inv = 1.0f / bcast;

    out[b * S_DIM + tid]           = x0 * inv;
    out[b * S_DIM + tid + THREADS] = x1 * inv;
}

extern "C" void kernel_launch(void* const* d_in, const int* in_sizes, int n_in,
                              void* d_out, int out_size) {
    const float* questions = (const float*)d_in[0];
    const float* facts     = (const float*)d_in[1];
    if (n_in >= 2 && in_sizes[0] > in_sizes[1]) {   // facts is the big one
        questions = (const float*)d_in[1];
        facts     = (const float*)d_in[0];
    }
    float* out = (float*)d_out;

    fused_kernel<<<B_DIM * CHUNKS, THREADS>>>(questions, facts, out);
}

// round 3
// speedup vs baseline: 1.1215x; 1.1215x over previous
#include <cuda_runtime.h>
#include <cuda_bf16.h>
#include <math_constants.h>

#define B_DIM 64
#define S_DIM 512
#define H_DIM 4096
#define WARPS_PER_BLOCK 8
#define THREADS (WARPS_PER_BLOCK * 32)
#define ROWS_PER_WARP 2
#define S_PER_BLOCK (WARPS_PER_BLOCK * ROWS_PER_WARP)   // 16
#define CHUNKS (S_DIM / S_PER_BLOCK)                     // 32 blocks per batch

// Scratch (no cudaMalloc allowed): energies [B, S] + per-batch completion counters
__device__ float        g_energies[B_DIM * S_DIM];
__device__ unsigned int g_counter[B_DIM];   // zero-init; reset by last block each replay

__global__ __launch_bounds__(THREADS, 3)    // cap regs (~85) -> 3 CTAs/SM, 24 warps
void fused_kernel(const float* __restrict__ questions,
                  const float* __restrict__ facts,
                  float* __restrict__ out) {
    __shared__ float4 sq[H_DIM / 4];          // 16 KB question row
    __shared__ float  red[WARPS_PER_BLOCK];
    __shared__ float  bcast;
    __shared__ int    is_last;

    const int b      = blockIdx.x / CHUNKS;
    const int schunk = blockIdx.x % CHUNKS;
    const int tid    = threadIdx.x;
    const int warp   = tid >> 5;
    const int lane   = tid & 31;

    // Stage this batch's question row into shared memory
    const float4* qv = reinterpret_cast<const float4*>(questions + (size_t)b * H_DIM);
    for (int i = tid; i < H_DIM / 4; i += THREADS)
        sq[i] = qv[i];
    __syncthreads();

    // ---- energies: each warp computes ROWS_PER_WARP dot products over H=4096 ----
    #pragma unroll
    for (int t = 0; t < ROWS_PER_WARP; ++t) {
        const int s = schunk * S_PER_BLOCK + t * WARPS_PER_BLOCK + warp;
        const float4* fv = reinterpret_cast<const float4*>(
            facts + ((size_t)b * S_DIM + s) * H_DIM);

        float a0 = 0.f, a1 = 0.f, a2 = 0.f, a3 = 0.f;
        // 8 iterations of 4 batched streaming loads; unroll 2 -> ~8 LDG.128 in
        // flight per warp without exploding registers.
        #pragma unroll 2
        for (int j = 0; j < (H_DIM / 4) / 32; j += 4) {
            float4 f0 = __ldcs(&fv[(j + 0) * 32 + lane]);
            float4 f1 = __ldcs(&fv[(j + 1) * 32 + lane]);
            float4 f2 = __ldcs(&fv[(j + 2) * 32 + lane]);
            float4 f3 = __ldcs(&fv[(j + 3) * 32 + lane]);
            float4 q0 = sq[(j + 0) * 32 + lane];
            float4 q1 = sq[(j + 1) * 32 + lane];
            float4 q2 = sq[(j + 2) * 32 + lane];
            float4 q3 = sq[(j + 3) * 32 + lane];
            a0 = fmaf(f0.x, q0.x, fmaf(f0.y, q0.y, fmaf(f0.z, q0.z, fmaf(f0.w, q0.w, a0))));
            a1 = fmaf(f1.x, q1.x, fmaf(f1.y, q1.y, fmaf(f1.z, q1.z, fmaf(f1.w, q1.w, a1))));
            a2 = fmaf(f2.x, q2.x, fmaf(f2.y, q2.y, fmaf(f2.z, q2.z, fmaf(f2.w, q2.w, a2))));
            a3 = fmaf(f3.x, q3.x, fmaf(f3.y, q3.y, fmaf(f3.z, q3.z, fmaf(f3.w, q3.w, a3))));
        }
        float acc = (a0 + a1) + (a2 + a3);
        #pragma unroll
        for (int off = 16; off > 0; off >>= 1)
            acc += __shfl_xor_sync(0xffffffffu, acc, off);
        if (lane == 0)
            g_energies[b * S_DIM + s] = acc;
    }

    // ---- publish: last block of this batch performs the softmax ----
    __syncthreads();
    if (tid == 0) {
        __threadfence();
        unsigned prev = atomicAdd(&g_counter[b], 1u);
        is_last = (prev == CHUNKS - 1);
        if (is_last) {
            g_counter[b] = 0;        // reset for next graph replay
            __threadfence();
        }
    }
    __syncthreads();
    if (!is_last) return;

    // ---- softmax over the batch's 512 energies (256 threads, 2 elems each) ----
    float e0 = __ldcg(&g_energies[b * S_DIM + tid]);
    float e1 = __ldcg(&g_energies[b * S_DIM + tid + THREADS]);

    float m = fmaxf(e0, e1);
    #pragma unroll
    for (int off = 16; off > 0; off >>= 1)
        m = fmaxf(m, __shfl_xor_sync(0xffffffffu, m, off));
    if (lane == 0) red[warp] = m;
    __syncthreads();
    if (tid < 32) {
        float v = (lane < WARPS_PER_BLOCK) ? red[lane] : -CUDART_INF_F;
        #pragma unroll
        for (int off = 16; off > 0; off >>= 1)
            v = fmaxf(v, __shfl_xor_sync(0xffffffffu, v, off));
        if (lane == 0) bcast = v;
    }
    __syncthreads();
    const float row_max = bcast;

    float x0 = __expf(e0 - row_max);
    float x1 = __expf(e1 - row_max);
    float ssum = x0 + x1;
    #pragma unroll
    for (int off = 16; off > 0; off >>= 1)
        ssum += __shfl_xor_sync(0xffffffffu, ssum, off);
    __syncthreads();
    if (lane == 0) red[warp] = ssum;
    __syncthreads();
    if (tid < 32) {
        float v = (lane < WARPS_PER_BLOCK) ? red[lane] : 0.f;
        #pragma unroll
        for (int off = 16; off > 0; off >>= 1)
            v += __shfl_xor_sync(0xffffffffu, v, off);
        if (lane == 0) bcast = v;
    }
    __syncthreads();
    const float inv = 1.0f / bcast;

    out[b * S_DIM + tid]           = x0 * inv;
    out[b * S_DIM + tid + THREADS] = x1 * inv;
}

extern "C" void kernel_launch(void* const* d_in, const int* in_sizes, int n_in,
                              void* d_out, int out_size) {
    const float* questions = (const float*)d_in[0];
    const float* facts     = (const float*)d_in[1];
    if (n_in >= 2 && in_sizes[0] > in_sizes[1]) {   // facts is the big one
        questions = (const float*)d_in[1];
        facts     = (const float*)d_in[0];
    }
    float* out = (float*)d_out;

    fused_kernel<<<B_DIM * CHUNKS, THREADS>>>(questions, facts, out);
}